// round 6
// baseline (speedup 1.0000x reference)
#include <cuda_runtime.h>
#include <cuda_bf16.h>
#include <math.h>
#include <stdint.h>

#define N_NODES 10000
#define N_EDGES 320000
#define MUL 32

__device__ __align__(16) float g_wkv [N_EDGES * 256];   // per-edge MLP outputs [wk(128)|wv(128)]
__device__ __align__(16) float g_qpre[N_NODES * 1024];  // per-node precomputed query side
__device__ __align__(16) float g_z   [N_NODES * 4];     // attention normalizer per head
__device__ __align__(16) float g_agg [N_NODES * 256];   // unnormalized aggregation

#define INV3F 0.57735026918962576f
#define INVFAN 0.015625f

__device__ __forceinline__ uint32_t smem_u32(const void* p) {
    uint32_t a;
    asm("{ .reg .u64 t; cvta.to.shared.u64 t, %1; cvt.u32.u64 %0, t; }" : "=r"(a) : "l"(p));
    return a;
}

__device__ __forceinline__ void ldsm_x4(uint32_t* r, uint32_t addr) {
    asm volatile("ldmatrix.sync.aligned.m8n8.x4.shared.b16 {%0,%1,%2,%3}, [%4];"
        : "=r"(r[0]), "=r"(r[1]), "=r"(r[2]), "=r"(r[3]) : "r"(addr));
}

__device__ __forceinline__ void mma_bf16(float* c, const uint32_t* a, const uint32_t* b) {
    asm volatile("mma.sync.aligned.m16n8k16.row.col.f32.bf16.bf16.f32 "
        "{%0,%1,%2,%3}, {%4,%5,%6,%7}, {%8,%9}, {%0,%1,%2,%3};"
        : "+f"(c[0]), "+f"(c[1]), "+f"(c[2]), "+f"(c[3])
        : "r"(a[0]), "r"(a[1]), "r"(a[2]), "r"(a[3]), "r"(b[0]), "r"(b[1]));
}

// ---------------------------------------------------------------- zero scratch
__global__ void ek_zero_kernel() {
    int i = blockIdx.x * blockDim.x + threadIdx.x;
    int stride = gridDim.x * blockDim.x;
    float4 z4 = make_float4(0.f, 0.f, 0.f, 0.f);
    for (int j = i; j < N_NODES * 64; j += stride) ((float4*)g_agg)[j] = z4;
    for (int j = i; j < N_NODES;      j += stride) ((float4*)g_z)[j]   = z4;
}

// ---------------------------------------------------------------- Qpre precompute
__global__ void __launch_bounds__(256) ek_qpre_kernel(const float* __restrict__ nodef,
                                                      const float* __restrict__ wdot) {
    extern __shared__ float qsm[];
    float* s_w = qsm;            // 16384 floats
    float* s_x = qsm + 16384;    // 128 floats
    int t = threadIdx.x;
    for (int i = t; i < 16384; i += 256) s_w[i] = wdot[i];
    for (int nn = 0; nn < 10; nn++) {
        int n = blockIdx.x * 10 + nn;
        __syncthreads();
        if (t < 32) *(float4*)&s_x[t * 4] = *(const float4*)(nodef + (size_t)n * 128 + t * 4);
        __syncthreads();
#pragma unroll
        for (int rep = 0; rep < 4; rep++) {
            int o = t + rep * 256;
            int h = o >> 8, i = o & 255;
            float acc = 0.f;
            if (i < 64) {
                int p = (i < 32) ? 0 : 1;
                int v = i & 31;
                const float* W = s_w + (p * 4 + h) * 1024 + v;
#pragma unroll
                for (int u = 0; u < 32; u++) acc += s_x[u] * W[u * 32];
                acc *= INVFAN;
            } else {
                int p  = (i < 160) ? 2 : 3;
                int tt = (i < 160) ? (i - 64) : (i - 160);
                int d = tt >> 5, v = tt & 31;
                const float* W = s_w + (p * 4 + h) * 1024 + v;
#pragma unroll
                for (int u = 0; u < 32; u++) acc += s_x[32 + 3 * u + d] * W[u * 32];
                acc *= INVFAN * INV3F;
            }
            g_qpre[(size_t)n * 1024 + o] = acc;
        }
    }
}

// ---------------------------------------------------------------- tensor-core dual MLP
// 128 edges/block, 8 warps. Layer1 scalar (8->64 + gelu), split bf16 hi/lo in
// smem. Layer2: two GEMMs (Hk x Wk2, Hv x Wv2), each M=128 N=128 K=64, via
// mma.sync m16n8k16 bf16, 3 split passes, fp32 accum in registers.
// smem byte layout (bf16 regions, row stride 144 B = 72 bf16):
//   A_HI @      0 : [2 part][128 e][72]   36864 B
//   A_LO @  36864 :                        36864 B
//   B_HI @  73728 : [2 g][128 n][72]       36864 B
//   B_LO @ 110592 :                        36864 B
//   W1   @ 147456 : [2][512] f32            4096 B
//   B1   @ 151552 : [128]  f32               512 B      total 152064 B
#define MLPA_HI 0
#define MLPA_LO 36864
#define MLPB_HI 73728
#define MLPB_LO 110592
#define MLPW1   147456
#define MLPB1   151552
#define MLP_SMEM 152064

__global__ void __launch_bounds__(256, 1) ek_mlp_tc_kernel(const float* __restrict__ xattr,
    const float* __restrict__ wk1, const float* __restrict__ bk1, const float* __restrict__ wk2,
    const float* __restrict__ wv1, const float* __restrict__ bv1, const float* __restrict__ wv2) {
    extern __shared__ char smc[];
    uint32_t sb = smem_u32(smc);
    float* s_w1 = (float*)(smc + MLPW1);
    float* s_b1 = (float*)(smc + MLPB1);
    int t = threadIdx.x;
    int e0 = blockIdx.x * 128;

    // stage layer-1 weights/bias
    for (int i = t; i < 1024; i += 256) s_w1[i] = (i < 512) ? wk1[i] : wv1[i - 512];
    if (t < 128) s_b1[t] = (t < 64) ? bk1[t] : bv1[t - 64];

    // stage B = w2^T (rows n, cols k) as bf16 hi/lo
    for (int i = t; i < 16384; i += 256) {
        int g = i >> 13, r = i & 8191, n = r >> 6, k = r & 63;
        float val = (g ? wv2 : wk2)[k * 128 + n];
        __nv_bfloat16 hi = __float2bfloat16(val);
        __nv_bfloat16 lo = __float2bfloat16(val - __bfloat162float(hi));
        uint32_t off = (uint32_t)(g * 18432 + n * 144 + k * 2);
        *(__nv_bfloat16*)(smc + MLPB_HI + off) = hi;
        *(__nv_bfloat16*)(smc + MLPB_LO + off) = lo;
    }
    __syncthreads();

    // layer1: thread -> (edge, part); part 0 = hk, 1 = hv
    {
        int e = t & 127, part = t >> 7;
        const float4* xp = (const float4*)(xattr + (size_t)(e0 + e) * 8);
        float4 xa = xp[0], xb = xp[1];
        const float* w1 = s_w1 + part * 512;
        const float* bb = s_b1 + part * 64;
        uint32_t abase = (uint32_t)(part * 18432 + e * 144);
#pragma unroll 8
        for (int c = 0; c < 64; c++) {
            float acc = xa.x * w1[c]       + xa.y * w1[64 + c]  + xa.z * w1[128 + c] + xa.w * w1[192 + c]
                      + xb.x * w1[256 + c] + xb.y * w1[320 + c] + xb.z * w1[384 + c] + xb.w * w1[448 + c];
            acc = acc * 0.35355339059327373f + bb[c];
            float u2 = 0.7978845608028654f * (acc + 0.044715f * acc * acc * acc);
            float h = 0.5f * acc * (1.f + tanhf(u2));
            __nv_bfloat16 hi = __float2bfloat16(h);
            __nv_bfloat16 lo = __float2bfloat16(h - __bfloat162float(hi));
            *(__nv_bfloat16*)(smc + MLPA_HI + abase + c * 2) = hi;
            *(__nv_bfloat16*)(smc + MLPA_LO + abase + c * 2) = lo;
        }
    }
    __syncthreads();

    int w = t >> 5, lane = t & 31;
    int mt = w & 3, nh = w >> 2;
    uint32_t ra_off = (uint32_t)((mt * 32 + (lane & 15)) * 144 + (lane >> 4) * 16);
    uint32_t rb_off = (uint32_t)((nh * 64 + (lane & 7) + ((lane >> 4) << 3)) * 144 + ((lane >> 3) & 1) * 16);

#pragma unroll
    for (int g = 0; g < 2; g++) {
        uint32_t Ah = sb + MLPA_HI + g * 18432;
        uint32_t Al = sb + MLPA_LO + g * 18432;
        uint32_t Bh = sb + MLPB_HI + g * 18432;
        uint32_t Bl = sb + MLPB_LO + g * 18432;
        float acc[2][8][4];
#pragma unroll
        for (int ms = 0; ms < 2; ms++)
#pragma unroll
            for (int ns = 0; ns < 8; ns++)
#pragma unroll
                for (int j = 0; j < 4; j++) acc[ms][ns][j] = 0.f;

#pragma unroll
        for (int ks = 0; ks < 4; ks++) {
            uint32_t ahi[2][4], alo[2][4];
#pragma unroll
            for (int ms = 0; ms < 2; ms++) {
                uint32_t ra = ra_off + ms * (16 * 144) + ks * 32;
                ldsm_x4(ahi[ms], Ah + ra);
                ldsm_x4(alo[ms], Al + ra);
            }
#pragma unroll
            for (int np = 0; np < 4; np++) {
                uint32_t rb = rb_off + np * (16 * 144) + ks * 32;
                uint32_t bhi[4], blo[4];
                ldsm_x4(bhi, Bh + rb);
                ldsm_x4(blo, Bl + rb);
#pragma unroll
                for (int ms = 0; ms < 2; ms++) {
                    mma_bf16(acc[ms][np * 2],     ahi[ms], bhi);
                    mma_bf16(acc[ms][np * 2],     ahi[ms], blo);
                    mma_bf16(acc[ms][np * 2],     alo[ms], bhi);
                    mma_bf16(acc[ms][np * 2 + 1], ahi[ms], bhi + 2);
                    mma_bf16(acc[ms][np * 2 + 1], ahi[ms], blo + 2);
                    mma_bf16(acc[ms][np * 2 + 1], alo[ms], bhi + 2);
                }
            }
        }
        // store: C frag rows = m, cols = n
#pragma unroll
        for (int ms = 0; ms < 2; ms++) {
#pragma unroll
            for (int ns = 0; ns < 8; ns++) {
                int row = mt * 32 + ms * 16 + (lane >> 2);
                int col = g * 128 + nh * 64 + ns * 8 + (lane & 3) * 2;
                float* dst = g_wkv + (size_t)(e0 + row) * 256 + col;
                float2 o1 = make_float2(acc[ms][ns][0] * 0.125f, acc[ms][ns][1] * 0.125f);
                float2 o2 = make_float2(acc[ms][ns][2] * 0.125f, acc[ms][ns][3] * 0.125f);
                __stcs((float2*)dst, o1);
                __stcs((float2*)(dst + 8 * 256), o2);
            }
        }
    }
}

// ---------------------------------------------------------------- edge megakernel
__device__ __forceinline__ float feat_base(int i, const float* row,
                                           float ys, float yv0, float yv1, float yv2,
                                           int& widx) {
    if (i < 32) { widx = i; return row[i] * ys; }
    if (i < 64) {
        int u = i - 32; widx = i;
        return (row[32 + 3 * u] * yv0 + row[33 + 3 * u] * yv1 + row[34 + 3 * u] * yv2) * INV3F;
    }
    if (i < 160) {
        int tt = i - 64; int d = tt >> 5, u = tt & 31; widx = 64 + u;
        float yd = (d == 0) ? yv0 : ((d == 1) ? yv1 : yv2);
        return row[u] * yd;
    }
    {
        int tt = i - 160; int d = tt >> 5, u = tt & 31; widx = 96 + u;
        return row[32 + 3 * u + d] * ys;
    }
}

__device__ __forceinline__ int feat_head(int i) {
    if (i < 64) return (i & 31) >> 3;
    int tt = (i < 160) ? (i - 64) : (i - 160);
    return (tt & 31) >> 3;
}

__device__ __forceinline__ void red_v4(float* p, float a, float b, float c, float d) {
    asm volatile("red.global.add.v4.f32 [%0], {%1, %2, %3, %4};"
                 :: "l"(p), "f"(a), "f"(b), "f"(c), "f"(d) : "memory");
}

__global__ void __launch_bounds__(256) ek_edge_kernel(
    const int* __restrict__ esrc, const int* __restrict__ edst,
    const float* __restrict__ eattr, const float* __restrict__ ecut,
    const float* __restrict__ nodef) {
    __shared__ float s_row[8][136];
    __shared__ float s_w[8][256];
    int warp = threadIdx.x >> 5, lane = threadIdx.x & 31;
    int e = blockIdx.x * 8 + warp;
    if (e >= N_EDGES) return;

    int s = esrc[e], dd = edst[e];
    float4 ea = *(const float4*)(eattr + (size_t)e * 4);
    float ys = ea.x, yv0 = ea.y, yv1 = ea.z, yv2 = ea.w;
    float cw = ecut[e];

    *(float4*)&s_row[warp][lane * 4] = *(const float4*)(nodef + (size_t)s * 128 + lane * 4);
    const float4* wv4 = (const float4*)(g_wkv + (size_t)e * 256);
    *(float4*)&s_w[warp][lane * 4]       = __ldcs(wv4 + lane);
    *(float4*)&s_w[warp][128 + lane * 4] = __ldcs(wv4 + 32 + lane);
    __syncwarp();

    const float* row = s_row[warp];
    const float* wk  = s_w[warp];
    int iA = 4 * lane, iB = 128 + 4 * lane;

    float bA[4], bB[4];
    int   xA[4], xB[4];
#pragma unroll
    for (int j = 0; j < 4; j++) {
        bA[j] = feat_base(iA + j, row, ys, yv0, yv1, yv2, xA[j]);
        bB[j] = feat_base(iB + j, row, ys, yv0, yv1, yv2, xB[j]);
    }

    float kA[4], kB[4];
#pragma unroll
    for (int j = 0; j < 4; j++) { kA[j] = wk[xA[j]] * bA[j]; kB[j] = wk[xB[j]] * bB[j]; }

    const float4* q = (const float4*)(g_qpre + (size_t)dd * 1024);
    float dh[4];
#pragma unroll
    for (int h = 0; h < 4; h++) {
        float4 qa = q[h * 64 + lane];
        float4 qb = q[h * 64 + 32 + lane];
        dh[h] = qa.x * kA[0] + qa.y * kA[1] + qa.z * kA[2] + qa.w * kA[3]
              + qb.x * kB[0] + qb.y * kB[1] + qb.z * kB[2] + qb.w * kB[3];
    }
#pragma unroll
    for (int off = 16; off; off >>= 1) {
#pragma unroll
        for (int h = 0; h < 4; h++) dh[h] += __shfl_xor_sync(0xffffffffu, dh[h], off);
    }

    float ew[4], sa[4];
#pragma unroll
    for (int h = 0; h < 4; h++) {
        ew[h] = cw * expf(dh[h]);
        sa[h] = sqrtf(ew[h]);     // sqrt(expw); /sqrt(z) deferred to epilogue
    }
    if (lane == 0) red_v4(g_z + (size_t)dd * 4, ew[0], ew[1], ew[2], ew[3]);

    const float* wv = wk + 128;
    float vA[4], vB[4];
#pragma unroll
    for (int j = 0; j < 4; j++) {
        vA[j] = wv[xA[j]] * bA[j] * sa[feat_head(iA + j)];
        vB[j] = wv[xB[j]] * bB[j] * sa[feat_head(iB + j)];
    }
    red_v4(g_agg + (size_t)dd * 256 + iA, vA[0], vA[1], vA[2], vA[3]);
    red_v4(g_agg + (size_t)dd * 256 + iB, vB[0], vB[1], vB[2], vB[3]);
}

// ---------------------------------------------------------------- node epilogue
__global__ void __launch_bounds__(128) ek_out_kernel(const float* __restrict__ wls,
                                                     const float* __restrict__ wlv,
                                                     float* __restrict__ out) {
    __shared__ float s_ws[2048];
    __shared__ float s_wv[2048];
    __shared__ float s_s[64];
    __shared__ float s_v[192];
    __shared__ float s_sc[4];
    int t = threadIdx.x;
    for (int i = t; i < 2048; i += 128) { s_ws[i] = wls[i]; s_wv[i] = wlv[i]; }
    const float inv_l = 0.125f;

    for (int nn = 0; nn < 10; nn++) {
        int n = blockIdx.x * 10 + nn;
        __syncthreads();
        if (t < 4) {
            float zz = g_z[(size_t)n * 4 + t];
            s_sc[t] = (zz == 0.f) ? 1.f : (1.0f / sqrtf(zz));
        }
        __syncthreads();
        for (int i = t; i < 256; i += 128) {
            float val = g_agg[(size_t)n * 256 + i];
            if (i < 64) {
                s_s[i] = val * s_sc[(i & 31) >> 3];
            } else {
                int f = i - 64;
                int blk = (f < 96) ? 0 : 1;
                int r = f - blk * 96;
                int d = r >> 5, uu = r & 31;
                s_v[d * 64 + blk * 32 + uu] = val * s_sc[uu >> 3];
            }
        }
        __syncthreads();
        if (t < 32) {
            int w = t;
            float acc = 0.f;
#pragma unroll
            for (int u = 0; u < 64; u++) acc += s_s[u] * s_ws[u * 32 + w];
            out[(size_t)n * 128 + w] = acc * inv_l;
        } else {
            int o = t - 32;
            int d = o >> 5, w = o & 31;
            float acc = 0.f;
#pragma unroll
            for (int u = 0; u < 64; u++) acc += s_v[d * 64 + u] * s_wv[u * 32 + w];
            out[(size_t)n * 128 + 32 + w * 3 + d] = acc * inv_l;
        }
    }
}

// ---------------------------------------------------------------- launch
extern "C" void kernel_launch(void* const* d_in, const int* in_sizes, int n_in,
                              void* d_out, int out_size) {
    const int*   esrc  = (const int*)d_in[0];
    const int*   edst  = (const int*)d_in[1];
    const float* xattr = (const float*)d_in[2];
    const float* eattr = (const float*)d_in[3];
    const float* ecut  = (const float*)d_in[4];
    const float* nodef = (const float*)d_in[5];
    const float* wk1   = (const float*)d_in[6];
    const float* bk1   = (const float*)d_in[7];
    const float* wk2   = (const float*)d_in[8];
    const float* wv1   = (const float*)d_in[9];
    const float* bv1   = (const float*)d_in[10];
    const float* wv2   = (const float*)d_in[11];
    const float* wdot  = (const float*)d_in[12];
    const float* wls   = (const float*)d_in[13];
    const float* wlv   = (const float*)d_in[14];
    float* out = (float*)d_out;

    const int qpre_smem = 16512 * 4;   // 66,048 B
    cudaFuncSetAttribute(ek_qpre_kernel,   cudaFuncAttributeMaxDynamicSharedMemorySize, qpre_smem);
    cudaFuncSetAttribute(ek_mlp_tc_kernel, cudaFuncAttributeMaxDynamicSharedMemorySize, MLP_SMEM);

    ek_zero_kernel<<<1024, 256>>>();
    ek_qpre_kernel<<<N_NODES / 10, 256, qpre_smem>>>(nodef, wdot);
    ek_mlp_tc_kernel<<<N_EDGES / 128, 256, MLP_SMEM>>>(xattr, wk1, bk1, wk2, wv1, bv1, wv2);
    ek_edge_kernel<<<N_EDGES / 8, 256>>>(esrc, edst, eattr, ecut, nodef);
    ek_out_kernel<<<N_NODES / 10, 128>>>(wls, wlv, out);
}

// round 7
// speedup vs baseline: 1.0375x; 1.0375x over previous
#include <cuda_runtime.h>
#include <cuda_bf16.h>
#include <math.h>
#include <stdint.h>

#define N_NODES 10000
#define N_EDGES 320000
#define MUL 32

__device__ __align__(16) float    g_wkv [N_EDGES * 256];   // per-edge MLP outputs [wk(128)|wv(128)]
__device__ __align__(16) float    g_qpre[N_NODES * 1024];  // per-node precomputed query side
__device__ __align__(16) float    g_z   [N_NODES * 4];     // attention normalizer per head
__device__ __align__(16) float    g_agg [N_NODES * 256];   // unnormalized aggregation
__device__ __align__(16) uint32_t g_bfrag[64 * 256];       // prebuilt B mma fragments (64KB)
__device__ int g_cnt [N_NODES];
__device__ int g_off [N_NODES + 1];
__device__ int g_cur [N_NODES];
__device__ int g_eord[N_EDGES];

#define INV3F 0.57735026918962576f
#define INVFAN 0.015625f

__device__ __forceinline__ uint32_t smem_u32(const void* p) {
    uint32_t a;
    asm("{ .reg .u64 t; cvta.to.shared.u64 t, %1; cvt.u32.u64 %0, t; }" : "=r"(a) : "l"(p));
    return a;
}
__device__ __forceinline__ void ldsm_x4(uint32_t* r, uint32_t addr) {
    asm volatile("ldmatrix.sync.aligned.m8n8.x4.shared.b16 {%0,%1,%2,%3}, [%4];"
        : "=r"(r[0]), "=r"(r[1]), "=r"(r[2]), "=r"(r[3]) : "r"(addr));
}
__device__ __forceinline__ void mma_bf16(float* c, const uint32_t* a, const uint32_t* b) {
    asm volatile("mma.sync.aligned.m16n8k16.row.col.f32.bf16.bf16.f32 "
        "{%0,%1,%2,%3}, {%4,%5,%6,%7}, {%8,%9}, {%0,%1,%2,%3};"
        : "+f"(c[0]), "+f"(c[1]), "+f"(c[2]), "+f"(c[3])
        : "r"(a[0]), "r"(a[1]), "r"(a[2]), "r"(a[3]), "r"(b[0]), "r"(b[1]));
}

// ---------------------------------------------------------------- tiny init
__global__ void ek_zero0() {
    int i = blockIdx.x * blockDim.x + threadIdx.x;
    if (i < N_NODES) g_cnt[i] = 0;
}
// ---------------------------------------------------------------- histogram
__global__ void ek_hist(const int* __restrict__ edst) {
    int e = blockIdx.x * blockDim.x + threadIdx.x;
    if (e < N_EDGES) atomicAdd(&g_cnt[edst[e]], 1);
}
// ---------------------------------------------------------------- scan (1 block, 256 thr)
__global__ void __launch_bounds__(256) ek_scan() {
    __shared__ int s_part[256];
    int t = threadIdx.x;
    int base = t * 40;
    int s = 0;
    for (int i = 0; i < 40; i++) { int idx = base + i; if (idx < N_NODES) s += g_cnt[idx]; }
    s_part[t] = s;
    __syncthreads();
    for (int off = 1; off < 256; off <<= 1) {
        int v = (t >= off) ? s_part[t - off] : 0;
        __syncthreads();
        s_part[t] += v;
        __syncthreads();
    }
    int run = s_part[t] - s;   // exclusive prefix of this chunk
    for (int i = 0; i < 40; i++) {
        int idx = base + i;
        if (idx < N_NODES) { g_off[idx] = run; g_cur[idx] = run; run += g_cnt[idx]; }
    }
    if (t == 0) g_off[N_NODES] = N_EDGES;
}
// ---------------------------------------------------------------- scatter
__global__ void ek_scatter(const int* __restrict__ edst) {
    int e = blockIdx.x * blockDim.x + threadIdx.x;
    if (e < N_EDGES) {
        int pos = atomicAdd(&g_cur[edst[e]], 1);
        g_eord[pos] = e;
    }
}

// ---------------------------------------------------------------- B-fragment prep (1 block)
// Stage w2^T hi/lo bf16 in smem (ldmatrix layout, 144B row stride), run ldmatrix
// once, store each lane's fragment registers to g_bfrag. Consumed by ek_mlp via
// plain coalesced global loads (L1-resident, identical for all blocks).
__global__ void __launch_bounds__(256) ek_bfrag(const float* __restrict__ wk2,
                                                const float* __restrict__ wv2) {
    extern __shared__ char bsm[];   // 73728 B: hi [2g][128n][144B], lo at +36864
    uint32_t sb = smem_u32(bsm);
    int t = threadIdx.x, w = t >> 5, lane = t & 31;
    for (int i = t; i < 16384; i += 256) {
        int g = i >> 13, r = i & 8191, n = r >> 6, k = r & 63;
        float val = (g ? wv2 : wk2)[k * 128 + n];
        __nv_bfloat16 hi = __float2bfloat16(val);
        __nv_bfloat16 lo = __float2bfloat16(val - __bfloat162float(hi));
        uint32_t off = (uint32_t)(g * 18432 + n * 144 + k * 2);
        *(__nv_bfloat16*)(bsm + off)         = hi;
        *(__nv_bfloat16*)(bsm + 36864 + off) = lo;
    }
    __syncthreads();
    for (int idx = w; idx < 64; idx += 8) {
        int g = idx >> 5, nh = (idx >> 4) & 1, ks = (idx >> 2) & 3, np = idx & 3;
        uint32_t rb = (uint32_t)((nh * 64 + np * 16 + (lane & 7) + ((lane >> 4) << 3)) * 144
                                 + ((lane >> 3) & 1) * 16 + ks * 32 + g * 18432);
        uint32_t bhi[4], blo[4];
        ldsm_x4(bhi, sb + rb);
        ldsm_x4(blo, sb + 36864 + rb);
        uint32_t* dst = g_bfrag + idx * 256;
#pragma unroll
        for (int r = 0; r < 4; r++) { dst[lane * 4 + r] = bhi[r]; dst[128 + lane * 4 + r] = blo[r]; }
    }
}

// ---------------------------------------------------------------- Qpre precompute
__global__ void __launch_bounds__(256) ek_qpre_kernel(const float* __restrict__ nodef,
                                                      const float* __restrict__ wdot) {
    extern __shared__ float qsm[];
    float* s_w = qsm;            // 16384 floats
    float* s_x = qsm + 16384;    // 128 floats
    int t = threadIdx.x;
    for (int i = t; i < 16384; i += 256) s_w[i] = wdot[i];
    for (int nn = 0; nn < 10; nn++) {
        int n = blockIdx.x * 10 + nn;
        __syncthreads();
        if (t < 32) *(float4*)&s_x[t * 4] = *(const float4*)(nodef + (size_t)n * 128 + t * 4);
        __syncthreads();
#pragma unroll
        for (int rep = 0; rep < 4; rep++) {
            int o = t + rep * 256;
            int h = o >> 8, i = o & 255;
            float acc = 0.f;
            if (i < 64) {
                int p = (i < 32) ? 0 : 1;
                int v = i & 31;
                const float* W = s_w + (p * 4 + h) * 1024 + v;
#pragma unroll
                for (int u = 0; u < 32; u++) acc += s_x[u] * W[u * 32];
                acc *= INVFAN;
            } else {
                int p  = (i < 160) ? 2 : 3;
                int tt = (i < 160) ? (i - 64) : (i - 160);
                int d = tt >> 5, v = tt & 31;
                const float* W = s_w + (p * 4 + h) * 1024 + v;
#pragma unroll
                for (int u = 0; u < 32; u++) acc += s_x[32 + 3 * u + d] * W[u * 32];
                acc *= INVFAN * INV3F;
            }
            g_qpre[(size_t)n * 1024 + o] = acc;
        }
    }
}

// ---------------------------------------------------------------- tensor-core dual MLP
// 128 edges/block. A (hidden hi/lo) in smem; B fragments streamed from g_bfrag
// (global, L1-hot). smem: A 73728 + w1 4096 + b1 512 = 78336 B -> 2 CTAs/SM.
#define MLPA_LO 36864
#define MLPW1   73728
#define MLPB1   77824
#define MLP_SMEM 78336

__global__ void __launch_bounds__(256) ek_mlp_tc_kernel(const float* __restrict__ xattr,
    const float* __restrict__ wk1, const float* __restrict__ bk1,
    const float* __restrict__ wv1, const float* __restrict__ bv1) {
    extern __shared__ char smc[];
    uint32_t sb = smem_u32(smc);
    float* s_w1 = (float*)(smc + MLPW1);
    float* s_b1 = (float*)(smc + MLPB1);
    int t = threadIdx.x;
    int e0 = blockIdx.x * 128;

    for (int i = t; i < 1024; i += 256) s_w1[i] = (i < 512) ? wk1[i] : wv1[i - 512];
    if (t < 128) s_b1[t] = (t < 64) ? bk1[t] : bv1[t - 64];
    __syncthreads();

    // layer1: thread -> (edge, part); part 0 = hk, 1 = hv
    {
        int e = t & 127, part = t >> 7;
        const float4* xp = (const float4*)(xattr + (size_t)(e0 + e) * 8);
        float4 xa = xp[0], xb = xp[1];
        const float* w1 = s_w1 + part * 512;
        const float* bb = s_b1 + part * 64;
        uint32_t abase = (uint32_t)(part * 18432 + e * 144);
#pragma unroll 8
        for (int c = 0; c < 64; c++) {
            float acc = xa.x * w1[c]       + xa.y * w1[64 + c]  + xa.z * w1[128 + c] + xa.w * w1[192 + c]
                      + xb.x * w1[256 + c] + xb.y * w1[320 + c] + xb.z * w1[384 + c] + xb.w * w1[448 + c];
            acc = acc * 0.35355339059327373f + bb[c];
            float u2 = 0.7978845608028654f * (acc + 0.044715f * acc * acc * acc);
            float th;
            asm("tanh.approx.f32 %0, %1;" : "=f"(th) : "f"(u2));
            float h = 0.5f * acc * (1.f + th);
            __nv_bfloat16 hi = __float2bfloat16(h);
            __nv_bfloat16 lo = __float2bfloat16(h - __bfloat162float(hi));
            *(__nv_bfloat16*)(smc + abase + c * 2)           = hi;
            *(__nv_bfloat16*)(smc + MLPA_LO + abase + c * 2) = lo;
        }
    }
    __syncthreads();

    int w = t >> 5, lane = t & 31;
    int mt = w & 3, nh = w >> 2;
    uint32_t ra_off = (uint32_t)((mt * 32 + (lane & 15)) * 144 + (lane >> 4) * 16);

#pragma unroll
    for (int g = 0; g < 2; g++) {
        uint32_t Ah = sb + g * 18432;
        uint32_t Al = sb + MLPA_LO + g * 18432;
        float acc[2][8][4];
#pragma unroll
        for (int ms = 0; ms < 2; ms++)
#pragma unroll
            for (int ns = 0; ns < 8; ns++)
#pragma unroll
                for (int j = 0; j < 4; j++) acc[ms][ns][j] = 0.f;

#pragma unroll
        for (int ks = 0; ks < 4; ks++) {
            uint32_t ahi[2][4], alo[2][4];
#pragma unroll
            for (int ms = 0; ms < 2; ms++) {
                uint32_t ra = ra_off + ms * (16 * 144) + ks * 32;
                ldsm_x4(ahi[ms], Ah + ra);
                ldsm_x4(alo[ms], Al + ra);
            }
#pragma unroll
            for (int np = 0; np < 4; np++) {
                const uint32_t* fb = g_bfrag + ((g * 2 + nh) * 16 + ks * 4 + np) * 256;
                uint4 BH = __ldg((const uint4*)(fb + lane * 4));
                uint4 BL = __ldg((const uint4*)(fb + 128 + lane * 4));
                uint32_t bhi[4] = {BH.x, BH.y, BH.z, BH.w};
                uint32_t blo[4] = {BL.x, BL.y, BL.z, BL.w};
#pragma unroll
                for (int ms = 0; ms < 2; ms++) {
                    mma_bf16(acc[ms][np * 2],     ahi[ms], bhi);
                    mma_bf16(acc[ms][np * 2],     ahi[ms], blo);
                    mma_bf16(acc[ms][np * 2],     alo[ms], bhi);
                    mma_bf16(acc[ms][np * 2 + 1], ahi[ms], bhi + 2);
                    mma_bf16(acc[ms][np * 2 + 1], ahi[ms], blo + 2);
                    mma_bf16(acc[ms][np * 2 + 1], alo[ms], bhi + 2);
                }
            }
        }
#pragma unroll
        for (int ms = 0; ms < 2; ms++) {
#pragma unroll
            for (int ns = 0; ns < 8; ns++) {
                int row = mt * 32 + ms * 16 + (lane >> 2);
                int col = g * 128 + nh * 64 + ns * 8 + (lane & 3) * 2;
                float* dst = g_wkv + (size_t)(e0 + row) * 256 + col;
                float2 o1 = make_float2(acc[ms][ns][0] * 0.125f, acc[ms][ns][1] * 0.125f);
                float2 o2 = make_float2(acc[ms][ns][2] * 0.125f, acc[ms][ns][3] * 0.125f);
                __stcs((float2*)dst, o1);
                __stcs((float2*)(dst + 8 * 256), o2);
            }
        }
    }
}

// ---------------------------------------------------------------- per-dst edge kernel
__device__ __forceinline__ float feat_base(int i, const float* row,
                                           float ys, float yv0, float yv1, float yv2,
                                           int& widx) {
    if (i < 32) { widx = i; return row[i] * ys; }
    if (i < 64) {
        int u = i - 32; widx = i;
        return (row[32 + 3 * u] * yv0 + row[33 + 3 * u] * yv1 + row[34 + 3 * u] * yv2) * INV3F;
    }
    if (i < 160) {
        int tt = i - 64; int d = tt >> 5, u = tt & 31; widx = 64 + u;
        float yd = (d == 0) ? yv0 : ((d == 1) ? yv1 : yv2);
        return row[u] * yd;
    }
    {
        int tt = i - 160; int d = tt >> 5, u = tt & 31; widx = 96 + u;
        return row[32 + 3 * u + d] * ys;
    }
}
__device__ __forceinline__ int feat_head(int i) {
    if (i < 64) return (i & 31) >> 3;
    int tt = (i < 160) ? (i - 64) : (i - 160);
    return (tt & 31) >> 3;
}

#define DEG_CAP 160
__global__ void __launch_bounds__(256) ek_edge_dst(
    const int* __restrict__ esrc,
    const float* __restrict__ eattr, const float* __restrict__ ecut,
    const float* __restrict__ nodef) {
    __shared__ int   s_ids [8][DEG_CAP];
    __shared__ int   s_ids2[8][DEG_CAP];
    __shared__ float s_row [8][132];
    __shared__ float s_wkv [8][264];
    int warp = threadIdx.x >> 5, lane = threadIdx.x & 31;
    int dst = blockIdx.x * 8 + warp;
    if (dst >= N_NODES) return;

    int start = g_off[dst];
    int cnt   = g_off[dst + 1] - start;

    // register-resident Q row for this dst
    const float4* q = (const float4*)(g_qpre + (size_t)dst * 1024);
    float4 qa[4], qb[4];
#pragma unroll
    for (int h = 0; h < 4; h++) { qa[h] = q[h * 64 + lane]; qb[h] = q[h * 64 + 32 + lane]; }

    int iA = 4 * lane, iB = 128 + 4 * lane;
    float accA[4] = {0.f, 0.f, 0.f, 0.f}, accB[4] = {0.f, 0.f, 0.f, 0.f};
    float zz[4] = {0.f, 0.f, 0.f, 0.f};

    if (cnt > 0) {
        bool sorted = (cnt <= DEG_CAP);
        if (sorted) {
            for (int p = lane; p < cnt; p += 32) s_ids[warp][p] = g_eord[start + p];
            __syncwarp();
            for (int p = lane; p < cnt; p += 32) {
                int myid = s_ids[warp][p], r = 0;
                for (int j = 0; j < cnt; j++) r += (s_ids[warp][j] < myid);
                s_ids2[warp][r] = myid;
            }
            __syncwarp();
        }
        int eid = sorted ? s_ids2[warp][0] : g_eord[start];
        int s   = esrc[eid];
        for (int k2 = 0; k2 < cnt; k2++) {
            float4 ea = *(const float4*)(eattr + (size_t)eid * 4);
            float ys = ea.x, yv0 = ea.y, yv1 = ea.z, yv2 = ea.w;
            float cw = ecut[eid];
            *(float4*)&s_row[warp][lane * 4] = *(const float4*)(nodef + (size_t)s * 128 + lane * 4);
            const float4* wv4 = (const float4*)(g_wkv + (size_t)eid * 256);
            *(float4*)&s_wkv[warp][lane * 4]       = __ldcs(wv4 + lane);
            *(float4*)&s_wkv[warp][128 + lane * 4] = __ldcs(wv4 + 32 + lane);
            // prefetch next edge's id/src while memory settles
            int eid_n = 0, s_n = 0;
            if (k2 + 1 < cnt) {
                eid_n = sorted ? s_ids2[warp][k2 + 1] : g_eord[start + k2 + 1];
                s_n = esrc[eid_n];
            }
            __syncwarp();

            const float* row = s_row[warp];
            const float* wk  = s_wkv[warp];
            float bA[4], bB[4];
            int   xA[4], xB[4];
#pragma unroll
            for (int j = 0; j < 4; j++) {
                bA[j] = feat_base(iA + j, row, ys, yv0, yv1, yv2, xA[j]);
                bB[j] = feat_base(iB + j, row, ys, yv0, yv1, yv2, xB[j]);
            }
            float kA[4], kB[4];
#pragma unroll
            for (int j = 0; j < 4; j++) { kA[j] = wk[xA[j]] * bA[j]; kB[j] = wk[xB[j]] * bB[j]; }

            float dh[4];
#pragma unroll
            for (int h = 0; h < 4; h++) {
                dh[h] = qa[h].x * kA[0] + qa[h].y * kA[1] + qa[h].z * kA[2] + qa[h].w * kA[3]
                      + qb[h].x * kB[0] + qb[h].y * kB[1] + qb[h].z * kB[2] + qb[h].w * kB[3];
            }
#pragma unroll
            for (int off = 16; off; off >>= 1) {
#pragma unroll
                for (int h = 0; h < 4; h++) dh[h] += __shfl_xor_sync(0xffffffffu, dh[h], off);
            }
            float sa[4];
#pragma unroll
            for (int h = 0; h < 4; h++) {
                float ew = cw * expf(dh[h]);
                zz[h] += ew;
                sa[h] = sqrtf(ew);
            }
            const float* wv = wk + 128;
#pragma unroll
            for (int j = 0; j < 4; j++) {
                accA[j] += wv[xA[j]] * bA[j] * sa[feat_head(iA + j)];
                accB[j] += wv[xB[j]] * bB[j] * sa[feat_head(iB + j)];
            }
            __syncwarp();
            eid = eid_n; s = s_n;
        }
    }
    if (lane == 0) *(float4*)(g_z + (size_t)dst * 4) = make_float4(zz[0], zz[1], zz[2], zz[3]);
    *(float4*)(g_agg + (size_t)dst * 256 + iA) = make_float4(accA[0], accA[1], accA[2], accA[3]);
    *(float4*)(g_agg + (size_t)dst * 256 + iB) = make_float4(accB[0], accB[1], accB[2], accB[3]);
}

// ---------------------------------------------------------------- node epilogue
__global__ void __launch_bounds__(128) ek_out_kernel(const float* __restrict__ wls,
                                                     const float* __restrict__ wlv,
                                                     float* __restrict__ out) {
    __shared__ float s_ws[2048];
    __shared__ float s_wv[2048];
    __shared__ float s_s[64];
    __shared__ float s_v[192];
    __shared__ float s_sc[4];
    int t = threadIdx.x;
    for (int i = t; i < 2048; i += 128) { s_ws[i] = wls[i]; s_wv[i] = wlv[i]; }
    const float inv_l = 0.125f;

    for (int nn = 0; nn < 10; nn++) {
        int n = blockIdx.x * 10 + nn;
        __syncthreads();
        if (t < 4) {
            float zz = g_z[(size_t)n * 4 + t];
            s_sc[t] = (zz == 0.f) ? 1.f : (1.0f / sqrtf(zz));
        }
        __syncthreads();
        for (int i = t; i < 256; i += 128) {
            float val = g_agg[(size_t)n * 256 + i];
            if (i < 64) {
                s_s[i] = val * s_sc[(i & 31) >> 3];
            } else {
                int f = i - 64;
                int blk = (f < 96) ? 0 : 1;
                int r = f - blk * 96;
                int d = r >> 5, uu = r & 31;
                s_v[d * 64 + blk * 32 + uu] = val * s_sc[uu >> 3];
            }
        }
        __syncthreads();
        if (t < 32) {
            int w = t;
            float acc = 0.f;
#pragma unroll
            for (int u = 0; u < 64; u++) acc += s_s[u] * s_ws[u * 32 + w];
            out[(size_t)n * 128 + w] = acc * inv_l;
        } else {
            int o = t - 32;
            int d = o >> 5, w = o & 31;
            float acc = 0.f;
#pragma unroll
            for (int u = 0; u < 64; u++) acc += s_v[d * 64 + u] * s_wv[u * 32 + w];
            out[(size_t)n * 128 + 32 + w * 3 + d] = acc * inv_l;
        }
    }
}

// ---------------------------------------------------------------- launch
extern "C" void kernel_launch(void* const* d_in, const int* in_sizes, int n_in,
                              void* d_out, int out_size) {
    const int*   esrc  = (const int*)d_in[0];
    const int*   edst  = (const int*)d_in[1];
    const float* xattr = (const float*)d_in[2];
    const float* eattr = (const float*)d_in[3];
    const float* ecut  = (const float*)d_in[4];
    const float* nodef = (const float*)d_in[5];
    const float* wk1   = (const float*)d_in[6];
    const float* bk1   = (const float*)d_in[7];
    const float* wk2   = (const float*)d_in[8];
    const float* wv1   = (const float*)d_in[9];
    const float* bv1   = (const float*)d_in[10];
    const float* wv2   = (const float*)d_in[11];
    const float* wdot  = (const float*)d_in[12];
    const float* wls   = (const float*)d_in[13];
    const float* wlv   = (const float*)d_in[14];
    float* out = (float*)d_out;

    const int qpre_smem  = 16512 * 4;   // 66,048 B
    const int bfrag_smem = 73728;
    cudaFuncSetAttribute(ek_qpre_kernel,   cudaFuncAttributeMaxDynamicSharedMemorySize, qpre_smem);
    cudaFuncSetAttribute(ek_bfrag,         cudaFuncAttributeMaxDynamicSharedMemorySize, bfrag_smem);
    cudaFuncSetAttribute(ek_mlp_tc_kernel, cudaFuncAttributeMaxDynamicSharedMemorySize, MLP_SMEM);

    ek_zero0<<<(N_NODES + 255) / 256, 256>>>();
    ek_hist<<<N_EDGES / 256, 256>>>(edst);
    ek_scan<<<1, 256>>>();
    ek_scatter<<<N_EDGES / 256, 256>>>(edst);
    ek_bfrag<<<1, 256, bfrag_smem>>>(wk2, wv2);
    ek_qpre_kernel<<<N_NODES / 10, 256, qpre_smem>>>(nodef, wdot);
    ek_mlp_tc_kernel<<<N_EDGES / 128, 256, MLP_SMEM>>>(xattr, wk1, bk1, wv1, bv1);
    ek_edge_dst<<<(N_NODES + 7) / 8, 256>>>(esrc, eattr, ecut, nodef);
    ek_out_kernel<<<N_NODES / 10, 128>>>(wls, wlv, out);
}